// round 9
// baseline (speedup 1.0000x reference)
#include <cuda_runtime.h>
#include <cuda_bf16.h>

// Problem constants
#define S_LEN   5000
#define BATCH   64
#define EMB     128
#define EMB4    32                 // float4 per row

// Output layout: [NFEs | PFEs | visited_time] flattened, all as float32
#define NFE_OFF 0
#define PFE_OFF ((size_t)BATCH * S_LEN * EMB)          // 40,960,000 floats
#define VT_OFF  ((size_t)2 * BATCH * S_LEN * EMB)      // 81,920,000 floats

#define THREADS        1024
#define CHASE_BLOCKS   64
#define TOTAL_BLOCKS   296          // 2 CTAs x 148 SMs = exactly one full wave

// Unified work space in float4 units: [0,U_NFE) NFE, [U_NFE,SPACE_END) PFE.
#define U_NFE        10240000u                 // BATCH*S_LEN*EMB4
#define SPACE_END    20480000u
#define PFE_B_STRIDE 160000u                   // S_LEN*EMB4 units per batch

// Guided scheduling: 128KB chunks first, 32KB chunks for the tail.
#define BIG_STEP     8192u                     // 128KB
#define SMALL_STEP   2048u                     // 32KB
#define BIG_END      18350080u                 // 2240*8192 (mult of 8192; > U_NFE)
// tail = SPACE_END-BIG_END = 2,129,920 = 1040 small chunks

#define NULL16 0xFFFFu

// Persistent scratch (zero-init at module load; self-reset at end of launch)
__device__ unsigned       g_cur;               // big-chunk cursor (units)
__device__ unsigned       g_small;             // small-chunk cursor (tail units)
__device__ unsigned       g_done;
__device__ int            g_ready[BATCH];
__device__ unsigned short g_idx[BATCH * S_LEN];

__global__ __launch_bounds__(THREADS, 2)
void embeddingnet_fused(const float* __restrict__ x,
                        const float* __restrict__ W,
                        const float* __restrict__ pattern,
                        const int*   __restrict__ sol,
                        float*       __restrict__ out)
{
    __shared__ unsigned bufA[S_LEN];
    __shared__ unsigned bufB[S_LEN];
    __shared__ unsigned s_p;
    __shared__ int      s_inbig;

    const int bid  = blockIdx.x;
    const int t    = threadIdx.x;
    const int lane = t & 31;

    // Hoisted W: column group is loop-invariant (unit & 31 == lane)
    const float4* __restrict__ W4 = (const float4*)W;
    const float4 wlo = W4[lane * 2];
    const float4 whi = W4[lane * 2 + 1];

    if (t == 0) s_inbig = 1;

    // ============ Phase 1 (blocks 0..63): Wyllie list-ranking ============
    if (bid < CHASE_BLOCKS) {
        const int b = bid;
        const int* __restrict__ srow = sol + (size_t)b * S_LEN;

        // Packed state per node v: (next:16 | rank:16). next==NULL16 means
        // the chain has reached node 0; rank then holds distance(v -> 0).
        for (int v = t; v < S_LEN; v += THREADS) {
            unsigned s = (unsigned)srow[v];
            unsigned n = (s == 0u) ? NULL16 : s;
            bufA[v] = (n << 16) | 1u;
        }
        __syncthreads();

        unsigned* rd = bufA;
        unsigned* wr = bufB;
        #pragma unroll 1
        for (int it = 0; it < 13; ++it) {          // 2^13 >= 5000
            for (int v = t; v < S_LEN; v += THREADS) {
                unsigned c = rd[v];
                unsigned n = c >> 16;
                if (n != NULL16) {
                    unsigned cn = rd[n];
                    c = (cn & 0xFFFF0000u) | ((c + cn) & 0xFFFFu);
                }
                wr[v] = c;
            }
            __syncthreads();
            unsigned* tmp = rd; rd = wr; wr = tmp;
        }

        // idx(v) = visited_time(v) % S = S - r(v);  vt(v)=idx except v==0 -> S
        float* out_vt = out + VT_OFF + (size_t)b * S_LEN;
        unsigned short* idxrow = g_idx + (size_t)b * S_LEN;
        for (int v = t; v < S_LEN; v += THREADS) {
            int r   = (int)(rd[v] & 0xFFFFu);
            int idx = S_LEN - r;
            out_vt[v] = (float)((v == 0) ? S_LEN : idx);
            idxrow[v] = (unsigned short)idx;
        }
        __syncthreads();
        if (t == 0) {
            __threadfence();                        // publish idxrow
            atomicExch(&g_ready[b], 1);             // release flag
        }
    }
    __syncthreads();                                // covers s_inbig init

    // ============ Phase 2 (all blocks): guided dynamic pool ============
    const float2* __restrict__ x2   = (const float2*)x;
    const float4* __restrict__ pat4 = (const float4*)pattern;
    float4* __restrict__ nfe      = (float4*)(out + NFE_OFF);
    float4* __restrict__ pfe_base = (float4*)(out + PFE_OFF);

    for (;;) {
        if (t == 0) {
            unsigned p;
            if (s_inbig) {
                p = atomicAdd(&g_cur, BIG_STEP);
                if (p >= BIG_END) {                 // big region exhausted
                    s_inbig = 0;
                    p = BIG_END + atomicAdd(&g_small, SMALL_STEP);
                }
            } else {
                p = BIG_END + atomicAdd(&g_small, SMALL_STEP);
            }
            s_p = p;
        }
        __syncthreads();
        unsigned p = s_p;
        if (p >= SPACE_END) break;
        unsigned step = (p < BIG_END) ? BIG_STEP : SMALL_STEP;
        unsigned end  = p + step; if (end > SPACE_END) end = SPACE_END;

        if (p < U_NFE) {
            // --- NFE: always a full BIG chunk (alignment guarantees end<=U_NFE)
            long base = (long)p;
            #pragma unroll
            for (int k = 0; k < 8; ++k) {
                long u   = base + t + k * THREADS;
                float2 xv = x2[u >> 5];             // warp-uniform broadcast (L1-cached)
                float4 o;
                o.x = xv.x * wlo.x + xv.y * wlo.y;
                o.y = xv.x * wlo.z + xv.y * wlo.w;
                o.z = xv.x * whi.x + xv.y * whi.y;
                o.w = xv.x * whi.z + xv.y * whi.w;
                nfe[u] = o;                         // plain store: L2-deferred writeback
            }
        } else {
            // --- PFE: units w in [w0, wend) of the linear [B,S,EMB4] space
            unsigned w0   = p   - U_NFE;
            unsigned wend = end - U_NFE;
            int b0 = (int)(w0 / PFE_B_STRIDE);
            int b1 = (int)((wend - 1u) / PFE_B_STRIDE);

            if (t == 0) {                           // acquire producer flag(s)
                volatile int* rf = g_ready;
                while (rf[b0] == 0) { }
                while (rf[b1] == 0) { }
                __threadfence();
            }
            __syncthreads();

            #pragma unroll 2
            for (unsigned w = w0 + t; w < wend; w += THREADS) {
                unsigned b = w / PFE_B_STRIDE;      // warp-uniform
                unsigned r = w - b * PFE_B_STRIDE;
                unsigned v = r >> 5;
                unsigned col = r & 31;
                unsigned idx = g_idx[b * S_LEN + v];
                pfe_base[w] = pat4[(size_t)idx * EMB4 + col];
            }
        }
        __syncthreads();                            // s_p / s_inbig reuse guard
    }

    // ============ Finalize: last finished block resets pool state ============
    if (t == 0) {
        unsigned d = atomicAdd(&g_done, 1u);
        if (d == TOTAL_BLOCKS - 1) {                // all blocks past the pool
            g_cur   = 0u;
            g_small = 0u;
            g_done  = 0u;
            #pragma unroll
            for (int b = 0; b < BATCH; ++b) g_ready[b] = 0;
            __threadfence();
        }
    }
}

extern "C" void kernel_launch(void* const* d_in, const int* in_sizes, int n_in,
                              void* d_out, int out_size)
{
    const float* x       = (const float*)d_in[0];   // [64,5000,2]
    const float* W       = (const float*)d_in[1];   // [128,2]
    const float* pattern = (const float*)d_in[2];   // [5000,128]
    const int*   sol     = (const int*)  d_in[3];   // [64,5000]
    float* out = (float*)d_out;

    embeddingnet_fused<<<TOTAL_BLOCKS, THREADS>>>(x, W, pattern, sol, out);
}

// round 10
// speedup vs baseline: 1.0412x; 1.0412x over previous
#include <cuda_runtime.h>
#include <cuda_bf16.h>

// Problem constants
#define S_LEN   5000
#define BATCH   64
#define EMB     128
#define EMB4    32                 // float4 per row

// Output layout: [NFEs | PFEs | visited_time] flattened, all as float32
#define NFE_OFF 0
#define PFE_OFF ((size_t)BATCH * S_LEN * EMB)          // 40,960,000 floats
#define VT_OFF  ((size_t)2 * BATCH * S_LEN * EMB)      // 81,920,000 floats

#define THREADS        1024
#define CHASE_BLOCKS   64
#define TOTAL_BLOCKS   296          // 2 CTAs x 148 SMs = exactly one full wave

// Unified work space in float4 units: [0,U_NFE) NFE, [U_NFE,SPACE_END) PFE.
#define U_NFE        10240000u                 // BATCH*S_LEN*EMB4
#define SPACE_END    20480000u
#define PFE_B_STRIDE 160000u                   // S_LEN*EMB4 units per batch

// Guided scheduling: 128KB chunks first, 16KB chunks for the tail.
#define BIG_STEP     8192u                     // 128KB
#define SMALL_STEP   1024u                     // 16KB
#define BIG_END      18350080u                 // 2240*8192 (mult of 8192; > U_NFE)
// tail = SPACE_END-BIG_END = 2,129,920 units = 2080 small chunks (exact)

#define NULL16 0xFFFFu

// Persistent scratch (zero-init at module load; self-reset at end of launch)
__device__ unsigned       g_cur;               // big-chunk cursor (units)
__device__ unsigned       g_small;             // small-chunk cursor (tail units)
__device__ unsigned       g_done;
__device__ int            g_ready[BATCH];
__device__ unsigned short g_idx[BATCH * S_LEN];

__global__ __launch_bounds__(THREADS, 2)
void embeddingnet_fused(const float* __restrict__ x,
                        const float* __restrict__ W,
                        const float* __restrict__ pattern,
                        const int*   __restrict__ sol,
                        float*       __restrict__ out)
{
    __shared__ unsigned bufA[S_LEN];
    __shared__ unsigned bufB[S_LEN];
    __shared__ unsigned s_p;
    __shared__ int      s_inbig;

    const int bid  = blockIdx.x;
    const int t    = threadIdx.x;
    const int lane = t & 31;

    // Hoisted W: column group is loop-invariant (unit & 31 == lane)
    const float4* __restrict__ W4 = (const float4*)W;
    const float4 wlo = W4[lane * 2];
    const float4 whi = W4[lane * 2 + 1];

    if (t == 0) s_inbig = 1;

    // ============ Phase 1 (blocks 0..63): Wyllie list-ranking ============
    if (bid < CHASE_BLOCKS) {
        const int b = bid;
        const int* __restrict__ srow = sol + (size_t)b * S_LEN;

        // Packed state per node v: (next:16 | rank:16). next==NULL16 means
        // the chain has reached node 0; rank then holds distance(v -> 0).
        for (int v = t; v < S_LEN; v += THREADS) {
            unsigned s = (unsigned)srow[v];
            unsigned n = (s == 0u) ? NULL16 : s;
            bufA[v] = (n << 16) | 1u;
        }
        __syncthreads();

        unsigned* rd = bufA;
        unsigned* wr = bufB;
        #pragma unroll 1
        for (int it = 0; it < 13; ++it) {          // 2^13 >= 5000
            for (int v = t; v < S_LEN; v += THREADS) {
                unsigned c = rd[v];
                unsigned n = c >> 16;
                if (n != NULL16) {
                    unsigned cn = rd[n];
                    c = (cn & 0xFFFF0000u) | ((c + cn) & 0xFFFFu);
                }
                wr[v] = c;
            }
            __syncthreads();
            unsigned* tmp = rd; rd = wr; wr = tmp;
        }

        // idx(v) = visited_time(v) % S = S - r(v);  vt(v)=idx except v==0 -> S
        float* out_vt = out + VT_OFF + (size_t)b * S_LEN;
        unsigned short* idxrow = g_idx + (size_t)b * S_LEN;
        for (int v = t; v < S_LEN; v += THREADS) {
            int r   = (int)(rd[v] & 0xFFFFu);
            int idx = S_LEN - r;
            __stcs(&out_vt[v], (float)((v == 0) ? S_LEN : idx));
            idxrow[v] = (unsigned short)idx;
        }
        __syncthreads();
        if (t == 0) {
            __threadfence();                        // publish idxrow
            atomicExch(&g_ready[b], 1);             // release flag
        }
    }
    __syncthreads();                                // covers s_inbig init

    // ============ Phase 2 (all blocks): guided dynamic pool ============
    const float2* __restrict__ x2   = (const float2*)x;
    const float4* __restrict__ pat4 = (const float4*)pattern;
    float4* __restrict__ nfe      = (float4*)(out + NFE_OFF);
    float4* __restrict__ pfe_base = (float4*)(out + PFE_OFF);

    for (;;) {
        if (t == 0) {
            unsigned p;
            if (s_inbig) {
                p = atomicAdd(&g_cur, BIG_STEP);
                if (p >= BIG_END) {                 // big region exhausted
                    s_inbig = 0;
                    p = BIG_END + atomicAdd(&g_small, SMALL_STEP);
                }
            } else {
                p = BIG_END + atomicAdd(&g_small, SMALL_STEP);
            }
            s_p = p;
        }
        __syncthreads();
        unsigned p = s_p;
        if (p >= SPACE_END) break;
        unsigned step = (p < BIG_END) ? BIG_STEP : SMALL_STEP;
        unsigned end  = p + step; if (end > SPACE_END) end = SPACE_END;

        if (p < U_NFE) {
            // --- NFE: always a full BIG chunk (alignment guarantees end<=U_NFE)
            long base = (long)p;
            #pragma unroll
            for (int k = 0; k < 8; ++k) {
                long u   = base + t + k * THREADS;
                float2 xv = x2[u >> 5];             // warp-uniform broadcast (L1-cached)
                float4 o;
                o.x = xv.x * wlo.x + xv.y * wlo.y;
                o.y = xv.x * wlo.z + xv.y * wlo.w;
                o.z = xv.x * whi.x + xv.y * whi.y;
                o.w = xv.x * whi.z + xv.y * whi.w;
                __stcs(&nfe[u], o);                 // streaming store: evict-first
            }
        } else {
            // --- PFE: units w in [w0, wend) of the linear [B,S,EMB4] space
            unsigned w0   = p   - U_NFE;
            unsigned wend = end - U_NFE;
            int b0 = (int)(w0 / PFE_B_STRIDE);
            int b1 = (int)((wend - 1u) / PFE_B_STRIDE);

            if (t == 0) {                           // acquire producer flag(s)
                volatile int* rf = g_ready;
                while (rf[b0] == 0) { }
                while (rf[b1] == 0) { }
                __threadfence();
            }
            __syncthreads();

            #pragma unroll 2
            for (unsigned w = w0 + t; w < wend; w += THREADS) {
                unsigned b = w / PFE_B_STRIDE;      // warp-uniform
                unsigned r = w - b * PFE_B_STRIDE;
                unsigned v = r >> 5;
                unsigned col = r & 31;
                unsigned idx = g_idx[b * S_LEN + v];
                float4 val = pat4[(size_t)idx * EMB4 + col];   // L2-resident
                __stcs(&pfe_base[w], val);
            }
        }
        __syncthreads();                            // s_p / s_inbig reuse guard
    }

    // ============ Finalize: last finished block resets pool state ============
    if (t == 0) {
        unsigned d = atomicAdd(&g_done, 1u);
        if (d == TOTAL_BLOCKS - 1) {                // all blocks past the pool
            g_cur   = 0u;
            g_small = 0u;
            g_done  = 0u;
            #pragma unroll
            for (int b = 0; b < BATCH; ++b) g_ready[b] = 0;
            __threadfence();
        }
    }
}

extern "C" void kernel_launch(void* const* d_in, const int* in_sizes, int n_in,
                              void* d_out, int out_size)
{
    const float* x       = (const float*)d_in[0];   // [64,5000,2]
    const float* W       = (const float*)d_in[1];   // [128,2]
    const float* pattern = (const float*)d_in[2];   // [5000,128]
    const int*   sol     = (const int*)  d_in[3];   // [64,5000]
    float* out = (float*)d_out;

    embeddingnet_fused<<<TOTAL_BLOCKS, THREADS>>>(x, W, pattern, sol, out);
}

// round 11
// speedup vs baseline: 1.1370x; 1.0920x over previous
#include <cuda_runtime.h>
#include <cuda_bf16.h>

// Problem constants
#define S_LEN   5000
#define BATCH   64
#define EMB     128
#define EMB4    32                 // float4 per row

// Output layout: [NFEs | PFEs | visited_time] flattened, all as float32
#define NFE_OFF 0
#define PFE_OFF ((size_t)BATCH * S_LEN * EMB)          // 40,960,000 floats
#define VT_OFF  ((size_t)2 * BATCH * S_LEN * EMB)      // 81,920,000 floats

#define THREADS        1024
#define CHASE_BLOCKS   64
#define TOTAL_BLOCKS   296          // 2 CTAs x 148 SMs = exactly one full wave

// Unified work space in float4 units: [0,U_NFE) NFE, [U_NFE,SPACE_END) PFE.
#define U_NFE        10240000u                 // BATCH*S_LEN*EMB4
#define SPACE_END    20480000u
#define PFE_B_STRIDE 160000u                   // S_LEN*EMB4 units per batch

// Guided scheduling: 128KB chunks first, 32KB chunks for the tail.
#define BIG_STEP     8192u                     // 128KB
#define SMALL_STEP   2048u                     // 32KB (2 units/thread — MLP floor)
#define BIG_END      18350080u                 // 2240*8192 (mult of 8192; > U_NFE)
// tail = SPACE_END-BIG_END = 2,129,920 units = 1040 small chunks

#define NULL16 0xFFFFu

// Persistent scratch (zero-init at module load; self-reset at end of launch)
__device__ unsigned       g_cur;               // big-chunk cursor (units)
__device__ unsigned       g_small;             // small-chunk cursor (tail units)
__device__ unsigned       g_done;
__device__ int            g_ready[BATCH];
__device__ unsigned short g_idx[BATCH * S_LEN];

__global__ __launch_bounds__(THREADS, 2)
void embeddingnet_fused(const float* __restrict__ x,
                        const float* __restrict__ W,
                        const float* __restrict__ pattern,
                        const int*   __restrict__ sol,
                        float*       __restrict__ out)
{
    __shared__ unsigned bufA[S_LEN];
    __shared__ unsigned bufB[S_LEN];
    __shared__ unsigned s_p;
    __shared__ int      s_inbig;

    const int bid  = blockIdx.x;
    const int t    = threadIdx.x;
    const int lane = t & 31;

    // Hoisted W: column group is loop-invariant (unit & 31 == lane)
    const float4* __restrict__ W4 = (const float4*)W;
    const float4 wlo = W4[lane * 2];
    const float4 whi = W4[lane * 2 + 1];

    if (t == 0) s_inbig = 1;

    // ============ Phase 1 (blocks 0..63): Wyllie list-ranking ============
    if (bid < CHASE_BLOCKS) {
        const int b = bid;
        const int* __restrict__ srow = sol + (size_t)b * S_LEN;

        // Packed state per node v: (next:16 | rank:16). next==NULL16 means
        // the chain has reached node 0; rank then holds distance(v -> 0).
        for (int v = t; v < S_LEN; v += THREADS) {
            unsigned s = (unsigned)srow[v];
            unsigned n = (s == 0u) ? NULL16 : s;
            bufA[v] = (n << 16) | 1u;
        }
        __syncthreads();

        unsigned* rd = bufA;
        unsigned* wr = bufB;
        #pragma unroll 1
        for (int it = 0; it < 13; ++it) {          // 2^13 >= 5000
            for (int v = t; v < S_LEN; v += THREADS) {
                unsigned c = rd[v];
                unsigned n = c >> 16;
                if (n != NULL16) {
                    unsigned cn = rd[n];
                    c = (cn & 0xFFFF0000u) | ((c + cn) & 0xFFFFu);
                }
                wr[v] = c;
            }
            __syncthreads();
            unsigned* tmp = rd; rd = wr; wr = tmp;
        }

        // idx(v) = visited_time(v) % S = S - r(v);  vt(v)=idx except v==0 -> S
        float* out_vt = out + VT_OFF + (size_t)b * S_LEN;
        unsigned short* idxrow = g_idx + (size_t)b * S_LEN;
        for (int v = t; v < S_LEN; v += THREADS) {
            int r   = (int)(rd[v] & 0xFFFFu);
            int idx = S_LEN - r;
            __stcs(&out_vt[v], (float)((v == 0) ? S_LEN : idx));
            idxrow[v] = (unsigned short)idx;
        }
        __syncthreads();
        if (t == 0) {
            __threadfence();                        // publish idxrow
            atomicExch(&g_ready[b], 1);             // release flag
        }
    }
    __syncthreads();                                // covers s_inbig init

    // ============ Phase 2 (all blocks): guided dynamic pool ============
    const float2* __restrict__ x2   = (const float2*)x;
    const float4* __restrict__ pat4 = (const float4*)pattern;
    float4* __restrict__ nfe      = (float4*)(out + NFE_OFF);
    float4* __restrict__ pfe_base = (float4*)(out + PFE_OFF);

    for (;;) {
        if (t == 0) {
            unsigned p;
            if (s_inbig) {
                p = atomicAdd(&g_cur, BIG_STEP);
                if (p >= BIG_END) {                 // big region exhausted
                    s_inbig = 0;
                    p = BIG_END + atomicAdd(&g_small, SMALL_STEP);
                }
            } else {
                p = BIG_END + atomicAdd(&g_small, SMALL_STEP);
            }
            s_p = p;
        }
        __syncthreads();
        unsigned p = s_p;
        if (p >= SPACE_END) break;
        unsigned step = (p < BIG_END) ? BIG_STEP : SMALL_STEP;
        unsigned end  = p + step; if (end > SPACE_END) end = SPACE_END;

        if (p < U_NFE) {
            // --- NFE: always a full BIG chunk (alignment guarantees end<=U_NFE)
            long base = (long)p;
            #pragma unroll
            for (int k = 0; k < 8; ++k) {
                long u   = base + t + k * THREADS;
                float2 xv = x2[u >> 5];             // warp-uniform broadcast (L1-cached)
                float4 o;
                o.x = xv.x * wlo.x + xv.y * wlo.y;
                o.y = xv.x * wlo.z + xv.y * wlo.w;
                o.z = xv.x * whi.x + xv.y * whi.y;
                o.w = xv.x * whi.z + xv.y * whi.w;
                __stcs(&nfe[u], o);                 // streaming store: evict-first
            }
        } else {
            // --- PFE: units w in [w0, wend) of the linear [B,S,EMB4] space
            unsigned w0   = p   - U_NFE;
            unsigned wend = end - U_NFE;
            int b0 = (int)(w0 / PFE_B_STRIDE);
            int b1 = (int)((wend - 1u) / PFE_B_STRIDE);

            if (t == 0) {                           // acquire producer flag(s)
                volatile int* rf = g_ready;
                while (rf[b0] == 0) { }
                while (rf[b1] == 0) { }
                __threadfence();
            }
            __syncthreads();

            #pragma unroll 2
            for (unsigned w = w0 + t; w < wend; w += THREADS) {
                unsigned b = w / PFE_B_STRIDE;      // warp-uniform
                unsigned r = w - b * PFE_B_STRIDE;
                unsigned v = r >> 5;
                unsigned col = r & 31;
                unsigned idx = g_idx[b * S_LEN + v];
                float4 val = pat4[(size_t)idx * EMB4 + col];   // L2-resident
                __stcs(&pfe_base[w], val);
            }
        }
        __syncthreads();                            // s_p / s_inbig reuse guard
    }

    // ============ Finalize: last finished block resets pool state ============
    if (t == 0) {
        unsigned d = atomicAdd(&g_done, 1u);
        if (d == TOTAL_BLOCKS - 1) {                // all blocks past the pool
            g_cur   = 0u;
            g_small = 0u;
            g_done  = 0u;
            #pragma unroll
            for (int b = 0; b < BATCH; ++b) g_ready[b] = 0;
            __threadfence();
        }
    }
}

extern "C" void kernel_launch(void* const* d_in, const int* in_sizes, int n_in,
                              void* d_out, int out_size)
{
    const float* x       = (const float*)d_in[0];   // [64,5000,2]
    const float* W       = (const float*)d_in[1];   // [128,2]
    const float* pattern = (const float*)d_in[2];   // [5000,128]
    const int*   sol     = (const int*)  d_in[3];   // [64,5000]
    float* out = (float*)d_out;

    embeddingnet_fused<<<TOTAL_BLOCKS, THREADS>>>(x, W, pattern, sol, out);
}